// round 5
// baseline (speedup 1.0000x reference)
#include <cuda_runtime.h>
#include <math.h>

// ---------------------------------------------------------------------------
// LinearDescent: linear attention with per-(b,h) 64x64 state reassociation.
// B=2, S=2048, H=1024, nh=16, hd=64, kg=8, din=128, P=2112, NPF=64.
// Round 5: ctx_out restructured for 2 CTAs/SM (8 tok/block, 2-head M stages).
// ---------------------------------------------------------------------------

#define TOK_TOTAL 4096
#define S_LEN     2048
#define H_DIM     1024
#define NH        16
#define P_DIM     2112
#define NPF       64
#define DIN       128

typedef unsigned long long u64;

__device__ __forceinline__ u64 pack2b(float v) {
    u64 r; asm("mov.b64 %0, {%1,%1};" : "=l"(r) : "f"(v)); return r;
}
__device__ __forceinline__ u64 ffma2(u64 a, u64 b, u64 c) {
    u64 d; asm("fma.rn.f32x2 %0, %1, %2, %3;" : "=l"(d) : "l"(a), "l"(b), "l"(c)); return d;
}
__device__ __forceinline__ float2 unpk(u64 v) {
    float2 f; asm("mov.b64 {%0,%1}, %2;" : "=f"(f.x), "=f"(f.y) : "l"(v)); return f;
}

// scratch (device globals; allocation-free kernel_launch)
__device__ float g_k1[TOK_TOTAL * H_DIM];
__device__ float g_k [TOK_TOTAL * H_DIM];
__device__ float g_v [TOK_TOTAL * H_DIM];
__device__ float g_Mall[32 * 4096];   // per-(b,h) 64x64 state (atomic accum)
__device__ float g_M0  [32 * 4096];   // prefix-chunk contribution

__device__ __forceinline__ int pos_idx(int s) { return (s < NPF) ? (S_LEN + s) : s; }

// ---------------------------------------------------------------------------
// K1: k1[t, g*128+e] = sum_d hidden[t, g*128+d] * Wk_group[g, d, e]
//     + zeroing duty for g_Mall / g_M0 (precedes mpart in stream order).
// ---------------------------------------------------------------------------
extern "C" __global__ void k1_kernel(const float* __restrict__ hidden,
                                     const float* __restrict__ Wkg) {
    extern __shared__ float sm[];
    float* Ws = sm;            // 128*128
    float* Xs = sm + 16384;    // 64*16
    const int g   = blockIdx.y;
    const int t0  = blockIdx.x * 64;
    const int tid = threadIdx.x;

    if (blockIdx.x < 32) {
        float4 z = make_float4(0.f, 0.f, 0.f, 0.f);
        if (g == 0) {
            float4* p = (float4*)(g_Mall + (size_t)blockIdx.x * 4096);
#pragma unroll
            for (int i = 0; i < 4; i++) p[tid + i * 256] = z;
        } else if (g == 1) {
            float4* p = (float4*)(g_M0 + (size_t)blockIdx.x * 4096);
#pragma unroll
            for (int i = 0; i < 4; i++) p[tid + i * 256] = z;
        }
    }

    {
        const float4* wsrc = (const float4*)(Wkg + (size_t)g * 16384);
        float4* wdst = (float4*)Ws;
#pragma unroll
        for (int i = 0; i < 16; i++) wdst[tid + i * 256] = wsrc[tid + i * 256];
    }

    const int ct = tid & 15;
    const int rt = tid >> 4;
    u64 acc2[4][4];
#pragma unroll
    for (int j = 0; j < 4; j++)
#pragma unroll
        for (int c = 0; c < 4; c++) acc2[j][c] = 0ull;

    for (int kk = 0; kk < 128; kk += 16) {
        __syncthreads();
        {
            int row = tid >> 2, c4 = tid & 3;
            ((float4*)Xs)[tid] =
                *(const float4*)(hidden + (size_t)(t0 + row) * H_DIM + g * DIN + kk + c4 * 4);
        }
        __syncthreads();
#pragma unroll
        for (int i = 0; i < 16; i++) {
            const ulonglong2* wp = (const ulonglong2*)&Ws[(kk + i) * 128 + ct * 8];
            ulonglong2 wA = wp[0], wB = wp[1];
#pragma unroll
            for (int j = 0; j < 4; j++) {
                u64 xb = pack2b(Xs[(rt * 4 + j) * 16 + i]);
                acc2[j][0] = ffma2(xb, wA.x, acc2[j][0]);
                acc2[j][1] = ffma2(xb, wA.y, acc2[j][1]);
                acc2[j][2] = ffma2(xb, wB.x, acc2[j][2]);
                acc2[j][3] = ffma2(xb, wB.y, acc2[j][3]);
            }
        }
    }
#pragma unroll
    for (int j = 0; j < 4; j++) {
        float* o = g_k1 + (size_t)(t0 + rt * 4 + j) * H_DIM + g * DIN + ct * 8;
        ((ulonglong2*)o)[0] = make_ulonglong2(acc2[j][0], acc2[j][1]);
        ((ulonglong2*)o)[1] = make_ulonglong2(acc2[j][2], acc2[j][3]);
    }
}

// ---------------------------------------------------------------------------
// K2: k and v (head/group mixing + positional adds). 16 tokens/block.
// ---------------------------------------------------------------------------
extern "C" __global__ void kv_kernel(const float* __restrict__ hidden,
                                     const float* __restrict__ Wkh,
                                     const float* __restrict__ Wv,
                                     const float* __restrict__ p_attn,
                                     const float* __restrict__ p_expand) {
    extern __shared__ float sm[];
    float* xs = sm;            // 16*1024
    float* ps = sm + 16384;    // 16*128
    const int tid  = threadIdx.x;
    const int tok0 = blockIdx.x * 16;

    {
        const float4* src = (const float4*)(hidden + (size_t)tok0 * H_DIM);
        float4* dst = (float4*)xs;
#pragma unroll
        for (int i = 0; i < 16; i++) dst[tid + i * 256] = src[tid + i * 256];
    }
#pragma unroll
    for (int i = 0; i < 8; i++) {
        int e = tid + i * 256;
        int t = e >> 7, c = e & 127;
        int s = (tok0 + t) & (S_LEN - 1);
        ps[e] = p_attn[(size_t)(64 + c) * P_DIM + pos_idx(s)];
    }
    __syncthreads();

    // ---- V ----
    {
        const int d  = tid & 63;
        const int g4 = tid >> 6;
        u64 acc2[2][16];
#pragma unroll
        for (int pp = 0; pp < 2; pp++)
#pragma unroll
            for (int t = 0; t < 16; t++) acc2[pp][t] = 0ull;
#pragma unroll
        for (int h = 0; h < NH; h++) {
            ulonglong2 w = *(const ulonglong2*)(Wv + d * 256 + h * 16 + g4 * 4);
#pragma unroll
            for (int t = 0; t < 16; t++) {
                u64 xb = pack2b(xs[t * 1024 + h * 64 + d]);
                acc2[0][t] = ffma2(xb, w.x, acc2[0][t]);
                acc2[1][t] = ffma2(xb, w.y, acc2[1][t]);
            }
        }
        float pe[4];
#pragma unroll
        for (int p = 0; p < 4; p++) pe[p] = p_expand[32 + g4 * 4 + p];
#pragma unroll
        for (int t = 0; t < 16; t++) {
            float pv = ps[t * 128 + 64 + d];
            float2 a01 = unpk(acc2[0][t]), a23 = unpk(acc2[1][t]);
            float* o = g_v + (size_t)(tok0 + t) * H_DIM + g4 * 256 + d;
            o[0]   = a01.x + pe[0] * pv;
            o[64]  = a01.y + pe[1] * pv;
            o[128] = a23.x + pe[2] * pv;
            o[192] = a23.y + pe[3] * pv;
        }
    }
    // ---- K ----
    __syncthreads();
    {
        const float4* src = (const float4*)(g_k1 + (size_t)tok0 * H_DIM);
        float4* dst = (float4*)xs;
#pragma unroll
        for (int i = 0; i < 16; i++) dst[tid + i * 256] = src[tid + i * 256];
    }
    __syncthreads();
    {
        const int dd = tid & 127;
        const int h2 = tid >> 7;
        u64 acc2[2][16];
#pragma unroll
        for (int pp = 0; pp < 2; pp++)
#pragma unroll
            for (int t = 0; t < 16; t++) acc2[pp][t] = 0ull;
#pragma unroll
        for (int g = 0; g < 8; g++) {
            ulonglong2 w = *(const ulonglong2*)(Wkh + dd * 64 + g * 8 + h2 * 4);
#pragma unroll
            for (int t = 0; t < 16; t++) {
                u64 xb = pack2b(xs[t * 1024 + g * 128 + dd]);
                acc2[0][t] = ffma2(xb, w.x, acc2[0][t]);
                acc2[1][t] = ffma2(xb, w.y, acc2[1][t]);
            }
        }
#pragma unroll
        for (int t = 0; t < 16; t++) {
            float2 a01 = unpk(acc2[0][t]), a23 = unpk(acc2[1][t]);
            float av[4] = {a01.x, a01.y, a23.x, a23.y};
#pragma unroll
            for (int p = 0; p < 4; p++) {
                int jj  = (h2 * 4 + p) * 128 + dd;
                int h16 = jj >> 6, d64 = jj & 63;
                float pe = p_expand[16 + h16];
                g_k[(size_t)(tok0 + t) * H_DIM + jj] = av[p] + pe * ps[t * 128 + d64];
            }
        }
    }
}

// ---------------------------------------------------------------------------
// K3: M partial per 64-token chunk -> RED.ADD into g_Mall (+plain g_M0, c=0)
// ---------------------------------------------------------------------------
extern "C" __global__ void mpart_kernel() {
    __shared__ float ks[64 * 64];
    __shared__ float vs[64 * 64];
    const int c = blockIdx.x, h = blockIdx.y, b = blockIdx.z;
    const int tid = threadIdx.x;
    const size_t tokbase = (size_t)(b * S_LEN + c * 64);
    const float* kp = g_k + tokbase * H_DIM + h * 64;
    const float* vp = g_v + tokbase * H_DIM + h * 64;
    for (int i = tid; i < 64 * 16; i += 128) {
        int row = i >> 4, c4 = i & 15;
        ((float4*)ks)[i] = *(const float4*)(kp + (size_t)row * H_DIM + c4 * 4);
        ((float4*)vs)[i] = *(const float4*)(vp + (size_t)row * H_DIM + c4 * 4);
    }
    __syncthreads();
    const int et = tid & 15;
    const int dt = tid >> 4;
    u64 acc2[8][2];
#pragma unroll
    for (int i = 0; i < 8; i++) { acc2[i][0] = 0ull; acc2[i][1] = 0ull; }
    for (int t = 0; t < 64; t++) {
        ulonglong2 v2 = *(ulonglong2*)&vs[t * 64 + et * 4];
        float4 ka = *(float4*)&ks[t * 64 + dt * 8];
        float4 kb = *(float4*)&ks[t * 64 + dt * 8 + 4];
        float kv[8] = {ka.x, ka.y, ka.z, ka.w, kb.x, kb.y, kb.z, kb.w};
#pragma unroll
        for (int i = 0; i < 8; i++) {
            u64 kb2 = pack2b(kv[i]);
            acc2[i][0] = ffma2(kb2, v2.x, acc2[i][0]);
            acc2[i][1] = ffma2(kb2, v2.y, acc2[i][1]);
        }
    }
    float* outp = g_Mall + (size_t)(b * 16 + h) * 4096;
    float* out0 = g_M0   + (size_t)(b * 16 + h) * 4096;
#pragma unroll
    for (int i = 0; i < 8; i++) {
        float2 a0 = unpk(acc2[i][0]), a1 = unpk(acc2[i][1]);
        int off = (dt * 8 + i) * 64 + et * 4;
        atomicAdd(&outp[off],     a0.x);
        atomicAdd(&outp[off + 1], a0.y);
        atomicAdd(&outp[off + 2], a1.x);
        atomicAdd(&outp[off + 3], a1.y);
        if (c == 0)
            *(ulonglong2*)&out0[off] = make_ulonglong2(acc2[i][0], acc2[i][1]);
    }
}

// ---------------------------------------------------------------------------
// K4: q (fused), ctx = q @ M(sel), Wc head-mix, gates, blend. 8 tokens/block,
// 2-head M stages, ~98KB smem -> 2 CTAs/SM.
// smem floats: xs [0,8192) | qs [8192,16384) (q->ctx) |
//              ms [16384,24576) (outs aliases) | psq [24576,25088) | gs.
// ---------------------------------------------------------------------------
extern "C" __global__ void __launch_bounds__(256, 2)
ctx_out_kernel(const float* __restrict__ hidden,
               const float* __restrict__ Wq,
               const float* __restrict__ p_attn,
               const float* __restrict__ p_expand,
               const float* __restrict__ Wc,
               const float* __restrict__ Wg,
               const float* __restrict__ Ug,
               const float* __restrict__ Vg,
               const float* __restrict__ bg,
               float* __restrict__ out) {
    extern __shared__ float sm[];
    float* xs   = sm;            // 8 tok x 1024 hidden (kept for gates/blend)
    float* qs   = sm + 8192;     // q, then ctx
    float* ms   = sm + 16384;    // 2-head M stage  -- outs aliases
    float* outs = sm + 16384;
    float* psq  = sm + 24576;    // 8 x 64
    float* gs   = sm + 25088;    // 16
    const int tid  = threadIdx.x;
    const int tok0 = blockIdx.x * 8;
    const int b    = tok0 / S_LEN;
    const int s0   = tok0 & (S_LEN - 1);
    const bool prefix = (s0 < NPF);

    {   // stage hidden (2048 float4)
        const float4* src = (const float4*)(hidden + (size_t)tok0 * H_DIM);
        float4* dst = (float4*)xs;
#pragma unroll
        for (int i = 0; i < 8; i++) dst[tid + i * 256] = src[tid + i * 256];
    }
#pragma unroll
    for (int i = 0; i < 2; i++) {   // stage psq (512 entries)
        int e = tid + i * 256;
        int t = e >> 6, d = e & 63;
        int s = (tok0 + t) & (S_LEN - 1);
        psq[e] = p_attn[(size_t)d * P_DIM + pos_idx(s)];
    }
    __syncthreads();

    // ---- Q (into qs) ----
    {
        const int d  = tid & 63;
        const int g4 = tid >> 6;
        u64 acc2[2][8];
#pragma unroll
        for (int pp = 0; pp < 2; pp++)
#pragma unroll
            for (int t = 0; t < 8; t++) acc2[pp][t] = 0ull;
#pragma unroll
        for (int h = 0; h < NH; h++) {
            ulonglong2 w = *(const ulonglong2*)(Wq + d * 256 + h * 16 + g4 * 4);
#pragma unroll
            for (int t = 0; t < 8; t++) {
                u64 xb = pack2b(xs[t * 1024 + h * 64 + d]);
                acc2[0][t] = ffma2(xb, w.x, acc2[0][t]);
                acc2[1][t] = ffma2(xb, w.y, acc2[1][t]);
            }
        }
        float pe[4];
#pragma unroll
        for (int p = 0; p < 4; p++) pe[p] = p_expand[g4 * 4 + p];
#pragma unroll
        for (int t = 0; t < 8; t++) {
            float pq = psq[t * 64 + d];
            float2 a01 = unpk(acc2[0][t]), a23 = unpk(acc2[1][t]);
            float* o = qs + t * 1024 + g4 * 256 + d;
            o[0]   = a01.x + pe[0] * pq;
            o[64]  = a01.y + pe[1] * pq;
            o[128] = a23.x + pe[2] * pq;
            o[192] = a23.y + pe[3] * pq;
        }
    }
    __syncthreads();

    // ---- ctx = q @ M, 8 stages of 2 heads ----
    const int h4 = tid >> 7;          // 0/1: head within stage
    const int r  = tid & 127;
    const int et = r & 15;            // e = et*4..+3
    const int tt = r >> 4;            // token 0..7
    const float* Ma = g_Mall + (size_t)(b * 16) * 4096;
    const float* M0 = g_M0   + (size_t)(b * 16) * 4096;

    for (int hh = 0; hh < 8; hh++) {
        {   // stage ms = 2 heads of M (2048 float4; 8/thread)
            const float4* msrc = (const float4*)(Ma + (size_t)hh * 8192);
            const float4* zsrc = (const float4*)(M0 + (size_t)hh * 8192);
            float4* mdst = (float4*)ms;
            if (prefix) {
#pragma unroll
                for (int i = 0; i < 8; i++) {
                    float4 A = msrc[tid + i * 256], Z = zsrc[tid + i * 256];
                    mdst[tid + i * 256] =
                        make_float4(A.x - Z.x, A.y - Z.y, A.z - Z.z, A.w - Z.w);
                }
            } else {
#pragma unroll
                for (int i = 0; i < 8; i++) mdst[tid + i * 256] = msrc[tid + i * 256];
            }
        }
        __syncthreads();
        u64 a0 = 0ull, a1 = 0ull;
        const float* qrow = qs + tt * 1024 + hh * 128 + h4 * 64;
        const float* mrow = ms + h4 * 4096 + et * 4;
#pragma unroll
        for (int dl = 0; dl < 64; dl++) {
            ulonglong2 m2 = *(ulonglong2*)&mrow[dl * 64];
            u64 qb = pack2b(qrow[dl]);
            a0 = ffma2(qb, m2.x, a0);
            a1 = ffma2(qb, m2.y, a1);
        }
        __syncthreads();   // all reads of ms + qs cols [hh*128,+128) done
        *(ulonglong2*)&qs[tt * 1024 + hh * 128 + h4 * 64 + et * 4] =
            make_ulonglong2(a0, a1);
        __syncthreads();   // ctx writes visible; ms free for restage
    }

    // ---- out = Wc head-mix (ctx in qs; outs aliases ms) ----
    {
        const int d  = tid & 63;
        const int g4 = tid >> 6;
        u64 acc2[2][8];
#pragma unroll
        for (int pp = 0; pp < 2; pp++)
#pragma unroll
            for (int t = 0; t < 8; t++) acc2[pp][t] = 0ull;
#pragma unroll
        for (int h = 0; h < NH; h++) {
            ulonglong2 w = *(const ulonglong2*)(Wc + d * 256 + h * 16 + g4 * 4);
#pragma unroll
            for (int t = 0; t < 8; t++) {
                u64 cb = pack2b(qs[t * 1024 + h * 64 + d]);
                acc2[0][t] = ffma2(cb, w.x, acc2[0][t]);
                acc2[1][t] = ffma2(cb, w.y, acc2[1][t]);
            }
        }
#pragma unroll
        for (int t = 0; t < 8; t++) {
            float2 a01 = unpk(acc2[0][t]), a23 = unpk(acc2[1][t]);
            float* o = outs + t * 1024 + g4 * 256 + d;
            o[0] = a01.x; o[64] = a01.y; o[128] = a23.x; o[192] = a23.y;
        }
    }
    __syncthreads();

    // ---- gates (one warp per token) ----
    {
        const int t = tid >> 5, sub = tid & 31;
        float a0 = 0.f, a1 = 0.f;
#pragma unroll 8
        for (int k = 0; k < 32; k++) {
            int j = sub + k * 32;
            float hv = xs[t * 1024 + j];
            float ov = outs[t * 1024 + j];
            a0 += hv * Wg[j]        + ov * Ug[j];
            a1 += hv * Wg[1024 + j] + ov * Ug[1024 + j];
        }
#pragma unroll
        for (int off = 16; off >= 1; off >>= 1) {
            a0 += __shfl_xor_sync(0xffffffffu, a0, off);
            a1 += __shfl_xor_sync(0xffffffffu, a1, off);
        }
        if (sub == 0) {
            int s  = (tok0 + t) & (S_LEN - 1);
            int ip = pos_idx(s);
            float z0 = a0 + Vg[ip] + bg[0];
            float z1 = a1 + Vg[P_DIM + ip] + bg[1];
            gs[t * 2]     = 1.f / (1.f + expf(-z0));
            gs[t * 2 + 1] = 1.f / (1.f + expf(-z1));
        }
    }
    __syncthreads();

    // ---- final blend ----
    {
        float4* od = (float4*)out;
#pragma unroll
        for (int i = 0; i < 8; i++) {
            int idx = tid + i * 256;          // float4 index, 2048 total
            int t = idx >> 8;
            float g0 = gs[t * 2], g1 = gs[t * 2 + 1];
            float4 ov = ((float4*)outs)[idx];
            float4 hv = ((float4*)xs)[idx];
            od[(size_t)tok0 * 256 + idx] =
                make_float4(g0 * ov.x + g1 * hv.x, g0 * ov.y + g1 * hv.y,
                            g0 * ov.z + g1 * hv.z, g0 * ov.w + g1 * hv.w);
        }
    }
}

// ---------------------------------------------------------------------------
extern "C" void kernel_launch(void* const* d_in, const int* in_sizes, int n_in,
                              void* d_out, int out_size) {
    const float* hidden   = (const float*)d_in[0];
    const float* Wq       = (const float*)d_in[3];
    const float* Wkg      = (const float*)d_in[4];
    const float* Wkh      = (const float*)d_in[5];
    const float* Wv       = (const float*)d_in[6];
    const float* p_attn   = (const float*)d_in[7];
    const float* p_expand = (const float*)d_in[8];
    const float* Wc       = (const float*)d_in[9];
    const float* Wg       = (const float*)d_in[10];
    const float* Ug       = (const float*)d_in[11];
    const float* Vg       = (const float*)d_in[12];
    const float* bg       = (const float*)d_in[13];
    float* out = (float*)d_out;

    cudaFuncSetAttribute(k1_kernel,      cudaFuncAttributeMaxDynamicSharedMemorySize, 69632);
    cudaFuncSetAttribute(kv_kernel,      cudaFuncAttributeMaxDynamicSharedMemorySize, 73728);
    cudaFuncSetAttribute(ctx_out_kernel, cudaFuncAttributeMaxDynamicSharedMemorySize, 100480);

    k1_kernel<<<dim3(64, 8), 256, 69632>>>(hidden, Wkg);
    kv_kernel<<<256, 256, 73728>>>(hidden, Wkh, Wv, p_attn, p_expand);
    mpart_kernel<<<dim3(32, 16, 2), 128>>>();
    ctx_out_kernel<<<512, 256, 100480>>>(hidden, Wq, p_attn, p_expand,
                                         Wc, Wg, Ug, Vg, bg, out);
}

// round 6
// speedup vs baseline: 1.0479x; 1.0479x over previous
#include <cuda_runtime.h>
#include <math.h>

// ---------------------------------------------------------------------------
// LinearDescent: linear attention with per-(b,h) 64x64 state reassociation.
// B=2, S=2048, H=1024, nh=16, hd=64, kg=8, din=128, P=2112, NPF=64.
// Round 6: revert to 16-tok K4 shape; 512-thread K4 (16 warps) and 512-thread
// kv (2 CTAs/SM). ffma2 packed math throughout.
// ---------------------------------------------------------------------------

#define TOK_TOTAL 4096
#define S_LEN     2048
#define H_DIM     1024
#define NH        16
#define P_DIM     2112
#define NPF       64
#define DIN       128

typedef unsigned long long u64;

__device__ __forceinline__ u64 pack2b(float v) {
    u64 r; asm("mov.b64 %0, {%1,%1};" : "=l"(r) : "f"(v)); return r;
}
__device__ __forceinline__ u64 ffma2(u64 a, u64 b, u64 c) {
    u64 d; asm("fma.rn.f32x2 %0, %1, %2, %3;" : "=l"(d) : "l"(a), "l"(b), "l"(c)); return d;
}
__device__ __forceinline__ float2 unpk(u64 v) {
    float2 f; asm("mov.b64 {%0,%1}, %2;" : "=f"(f.x), "=f"(f.y) : "l"(v)); return f;
}

// scratch (device globals; allocation-free kernel_launch)
__device__ float g_k1[TOK_TOTAL * H_DIM];
__device__ float g_k [TOK_TOTAL * H_DIM];
__device__ float g_v [TOK_TOTAL * H_DIM];
__device__ float g_Mall[32 * 4096];   // per-(b,h) 64x64 state (atomic accum)
__device__ float g_M0  [32 * 4096];   // prefix-chunk contribution

__device__ __forceinline__ int pos_idx(int s) { return (s < NPF) ? (S_LEN + s) : s; }

// ---------------------------------------------------------------------------
// K1: k1[t, g*128+e] = sum_d hidden[t, g*128+d] * Wk_group[g, d, e]
//     + zeroing duty for g_Mall / g_M0 (precedes mpart in stream order).
// ---------------------------------------------------------------------------
extern "C" __global__ void k1_kernel(const float* __restrict__ hidden,
                                     const float* __restrict__ Wkg) {
    extern __shared__ float sm[];
    float* Ws = sm;            // 128*128
    float* Xs = sm + 16384;    // 64*16
    const int g   = blockIdx.y;
    const int t0  = blockIdx.x * 64;
    const int tid = threadIdx.x;

    if (blockIdx.x < 32) {
        float4 z = make_float4(0.f, 0.f, 0.f, 0.f);
        if (g == 0) {
            float4* p = (float4*)(g_Mall + (size_t)blockIdx.x * 4096);
#pragma unroll
            for (int i = 0; i < 4; i++) p[tid + i * 256] = z;
        } else if (g == 1) {
            float4* p = (float4*)(g_M0 + (size_t)blockIdx.x * 4096);
#pragma unroll
            for (int i = 0; i < 4; i++) p[tid + i * 256] = z;
        }
    }

    {
        const float4* wsrc = (const float4*)(Wkg + (size_t)g * 16384);
        float4* wdst = (float4*)Ws;
#pragma unroll
        for (int i = 0; i < 16; i++) wdst[tid + i * 256] = wsrc[tid + i * 256];
    }

    const int ct = tid & 15;
    const int rt = tid >> 4;
    u64 acc2[4][4];
#pragma unroll
    for (int j = 0; j < 4; j++)
#pragma unroll
        for (int c = 0; c < 4; c++) acc2[j][c] = 0ull;

    for (int kk = 0; kk < 128; kk += 16) {
        __syncthreads();
        {
            int row = tid >> 2, c4 = tid & 3;
            ((float4*)Xs)[tid] =
                *(const float4*)(hidden + (size_t)(t0 + row) * H_DIM + g * DIN + kk + c4 * 4);
        }
        __syncthreads();
#pragma unroll
        for (int i = 0; i < 16; i++) {
            const ulonglong2* wp = (const ulonglong2*)&Ws[(kk + i) * 128 + ct * 8];
            ulonglong2 wA = wp[0], wB = wp[1];
#pragma unroll
            for (int j = 0; j < 4; j++) {
                u64 xb = pack2b(Xs[(rt * 4 + j) * 16 + i]);
                acc2[j][0] = ffma2(xb, wA.x, acc2[j][0]);
                acc2[j][1] = ffma2(xb, wA.y, acc2[j][1]);
                acc2[j][2] = ffma2(xb, wB.x, acc2[j][2]);
                acc2[j][3] = ffma2(xb, wB.y, acc2[j][3]);
            }
        }
    }
#pragma unroll
    for (int j = 0; j < 4; j++) {
        float* o = g_k1 + (size_t)(t0 + rt * 4 + j) * H_DIM + g * DIN + ct * 8;
        ((ulonglong2*)o)[0] = make_ulonglong2(acc2[j][0], acc2[j][1]);
        ((ulonglong2*)o)[1] = make_ulonglong2(acc2[j][2], acc2[j][3]);
    }
}

// ---------------------------------------------------------------------------
// K2: k and v projections. 16 tokens/block, 512 threads, 2 CTAs/SM.
// ---------------------------------------------------------------------------
extern "C" __global__ void __launch_bounds__(512, 2)
kv_kernel(const float* __restrict__ hidden,
          const float* __restrict__ Wkh,
          const float* __restrict__ Wv,
          const float* __restrict__ p_attn,
          const float* __restrict__ p_expand) {
    extern __shared__ float sm[];
    float* xs = sm;            // 16*1024
    float* ps = sm + 16384;    // 16*128  (p_attn rows 64..191)
    const int tid  = threadIdx.x;
    const int tok0 = blockIdx.x * 16;

    {
        const float4* src = (const float4*)(hidden + (size_t)tok0 * H_DIM);
        float4* dst = (float4*)xs;
#pragma unroll
        for (int i = 0; i < 8; i++) dst[tid + i * 512] = src[tid + i * 512];
    }
#pragma unroll
    for (int i = 0; i < 4; i++) {
        int e = tid + i * 512;          // 2048 entries
        int t = e >> 7, c = e & 127;
        int s = (tok0 + t) & (S_LEN - 1);
        ps[e] = p_attn[(size_t)(64 + c) * P_DIM + pos_idx(s)];
    }
    __syncthreads();

    // ---- V : thread = (d 0..63, g-pair 0..7); 8-token halves ----
    {
        const int d  = tid & 63;
        const int g8 = tid >> 6;
        const float pe0 = p_expand[32 + g8 * 2];
        const float pe1 = p_expand[33 + g8 * 2];
#pragma unroll
        for (int th = 0; th < 2; th++) {
            u64 acc[8];
#pragma unroll
            for (int t = 0; t < 8; t++) acc[t] = 0ull;
#pragma unroll
            for (int h = 0; h < NH; h++) {
                u64 w = *(const u64*)(Wv + d * 256 + h * 16 + g8 * 2);
#pragma unroll
                for (int t = 0; t < 8; t++)
                    acc[t] = ffma2(pack2b(xs[(th * 8 + t) * 1024 + h * 64 + d]), w, acc[t]);
            }
#pragma unroll
            for (int t = 0; t < 8; t++) {
                int tt = th * 8 + t;
                float pv = ps[tt * 128 + 64 + d];
                float2 a = unpk(acc[t]);
                float* o = g_v + (size_t)(tok0 + tt) * H_DIM + g8 * 128 + d;
                o[0]  = a.x + pe0 * pv;
                o[64] = a.y + pe1 * pv;
            }
        }
    }
    // ---- K ----
    __syncthreads();
    {
        const float4* src = (const float4*)(g_k1 + (size_t)tok0 * H_DIM);
        float4* dst = (float4*)xs;
#pragma unroll
        for (int i = 0; i < 8; i++) dst[tid + i * 512] = src[tid + i * 512];
    }
    __syncthreads();
    {
        const int dd = tid & 127;
        const int h4 = tid >> 7;   // h8 pair base = h4*2
        const int jj0 = (h4 * 2) * 128 + dd;
        const int jj1 = (h4 * 2 + 1) * 128 + dd;
        const float pe0 = p_expand[16 + (jj0 >> 6)];
        const float pe1 = p_expand[16 + (jj1 >> 6)];
        const int d0 = jj0 & 63, d1 = jj1 & 63;
#pragma unroll
        for (int th = 0; th < 2; th++) {
            u64 acc[8];
#pragma unroll
            for (int t = 0; t < 8; t++) acc[t] = 0ull;
#pragma unroll
            for (int g = 0; g < 8; g++) {
                u64 w = *(const u64*)(Wkh + dd * 64 + g * 8 + h4 * 2);
#pragma unroll
                for (int t = 0; t < 8; t++)
                    acc[t] = ffma2(pack2b(xs[(th * 8 + t) * 1024 + g * 128 + dd]), w, acc[t]);
            }
#pragma unroll
            for (int t = 0; t < 8; t++) {
                int tt = th * 8 + t;
                float2 a = unpk(acc[t]);
                float* kb = g_k + (size_t)(tok0 + tt) * H_DIM;
                kb[jj0] = a.x + pe0 * ps[tt * 128 + d0];
                kb[jj1] = a.y + pe1 * ps[tt * 128 + d1];
            }
        }
    }
}

// ---------------------------------------------------------------------------
// K3: M partial per 64-token chunk -> RED.ADD into g_Mall (+plain g_M0, c=0)
// ---------------------------------------------------------------------------
extern "C" __global__ void mpart_kernel() {
    __shared__ float ks[64 * 64];
    __shared__ float vs[64 * 64];
    const int c = blockIdx.x, h = blockIdx.y, b = blockIdx.z;
    const int tid = threadIdx.x;
    const size_t tokbase = (size_t)(b * S_LEN + c * 64);
    const float* kp = g_k + tokbase * H_DIM + h * 64;
    const float* vp = g_v + tokbase * H_DIM + h * 64;
    for (int i = tid; i < 64 * 16; i += 128) {
        int row = i >> 4, c4 = i & 15;
        ((float4*)ks)[i] = *(const float4*)(kp + (size_t)row * H_DIM + c4 * 4);
        ((float4*)vs)[i] = *(const float4*)(vp + (size_t)row * H_DIM + c4 * 4);
    }
    __syncthreads();
    const int et = tid & 15;
    const int dt = tid >> 4;
    u64 acc2[8][2];
#pragma unroll
    for (int i = 0; i < 8; i++) { acc2[i][0] = 0ull; acc2[i][1] = 0ull; }
    for (int t = 0; t < 64; t++) {
        ulonglong2 v2 = *(ulonglong2*)&vs[t * 64 + et * 4];
        float4 ka = *(float4*)&ks[t * 64 + dt * 8];
        float4 kb = *(float4*)&ks[t * 64 + dt * 8 + 4];
        float kv[8] = {ka.x, ka.y, ka.z, ka.w, kb.x, kb.y, kb.z, kb.w};
#pragma unroll
        for (int i = 0; i < 8; i++) {
            u64 kb2 = pack2b(kv[i]);
            acc2[i][0] = ffma2(kb2, v2.x, acc2[i][0]);
            acc2[i][1] = ffma2(kb2, v2.y, acc2[i][1]);
        }
    }
    float* outp = g_Mall + (size_t)(b * 16 + h) * 4096;
    float* out0 = g_M0   + (size_t)(b * 16 + h) * 4096;
#pragma unroll
    for (int i = 0; i < 8; i++) {
        float2 a0 = unpk(acc2[i][0]), a1 = unpk(acc2[i][1]);
        int off = (dt * 8 + i) * 64 + et * 4;
        atomicAdd(&outp[off],     a0.x);
        atomicAdd(&outp[off + 1], a0.y);
        atomicAdd(&outp[off + 2], a1.x);
        atomicAdd(&outp[off + 3], a1.y);
        if (c == 0)
            *(ulonglong2*)&out0[off] = make_ulonglong2(acc2[i][0], acc2[i][1]);
    }
}

// ---------------------------------------------------------------------------
// K4: q (fused), ctx = q @ M(sel), Wc head-mix, gates, blend.
// 16 tokens/block, 512 threads, 196KB smem, 1 CTA/SM (16 warps).
// smem floats: xs [0,16384) | qs [16384,32768) (q->ctx in place) |
//              ms [32768,49152) 4-head stage (outs aliases) | psq | gs.
// ---------------------------------------------------------------------------
extern "C" __global__ void __launch_bounds__(512, 1)
ctx_out_kernel(const float* __restrict__ hidden,
               const float* __restrict__ Wq,
               const float* __restrict__ p_attn,
               const float* __restrict__ p_expand,
               const float* __restrict__ Wc,
               const float* __restrict__ Wg,
               const float* __restrict__ Ug,
               const float* __restrict__ Vg,
               const float* __restrict__ bg,
               float* __restrict__ out) {
    extern __shared__ float sm[];
    float* xs   = sm;            // hidden (kept: gates + blend)
    float* qs   = sm + 16384;    // q, then ctx
    float* ms   = sm + 32768;    // 4-head M stage -- outs aliases
    float* outs = sm + 32768;
    float* psq  = sm + 49152;    // 16 x 64
    float* gs   = sm + 50176;    // 32
    const int tid  = threadIdx.x;
    const int tok0 = blockIdx.x * 16;
    const int b    = tok0 / S_LEN;
    const int s0   = tok0 & (S_LEN - 1);
    const bool prefix = (s0 < NPF);

    {   // stage hidden (4096 float4)
        const float4* src = (const float4*)(hidden + (size_t)tok0 * H_DIM);
        float4* dst = (float4*)xs;
#pragma unroll
        for (int i = 0; i < 8; i++) dst[tid + i * 512] = src[tid + i * 512];
    }
#pragma unroll
    for (int i = 0; i < 2; i++) {   // psq: 1024 entries
        int e = tid + i * 512;
        int t = e >> 6, d = e & 63;
        int s = (tok0 + t) & (S_LEN - 1);
        psq[e] = p_attn[(size_t)d * P_DIM + pos_idx(s)];
    }
    __syncthreads();

    // ---- Q : thread = (d, g-pair) ----
    {
        const int d  = tid & 63;
        const int g8 = tid >> 6;
        const float pe0 = p_expand[g8 * 2];
        const float pe1 = p_expand[g8 * 2 + 1];
        u64 acc[16];
#pragma unroll
        for (int t = 0; t < 16; t++) acc[t] = 0ull;
#pragma unroll
        for (int h = 0; h < NH; h++) {
            u64 w = *(const u64*)(Wq + d * 256 + h * 16 + g8 * 2);
#pragma unroll
            for (int t = 0; t < 16; t++)
                acc[t] = ffma2(pack2b(xs[t * 1024 + h * 64 + d]), w, acc[t]);
        }
#pragma unroll
        for (int t = 0; t < 16; t++) {
            float pq = psq[t * 64 + d];
            float2 a = unpk(acc[t]);
            float* o = qs + t * 1024 + g8 * 128 + d;
            o[0]  = a.x + pe0 * pq;
            o[64] = a.y + pe1 * pq;
        }
    }

    // ---- ctx = q @ M : 4 stages x 4 heads; thread tile 2 tok x 4 e ----
    const int h4 = tid >> 7;          // head within stage (0..3)
    const int r  = tid & 127;
    const int et = r & 15;            // e = et*4 .. +3
    const int tt = r >> 4;            // token pair base = tt*2
    const float* Ma = g_Mall + (size_t)(b * 16) * 4096;
    const float* M0 = g_M0   + (size_t)(b * 16) * 4096;

    for (int hh = 0; hh < 4; hh++) {
        __syncthreads();              // prior stage fully consumed
        {   // stage 4 heads of M (4096 float4, 8/thread)
            const float4* msrc = (const float4*)(Ma + (size_t)hh * 16384);
            const float4* zsrc = (const float4*)(M0 + (size_t)hh * 16384);
            float4* mdst = (float4*)ms;
            if (prefix) {
#pragma unroll
                for (int i = 0; i < 8; i++) {
                    float4 A = msrc[tid + i * 512], Z = zsrc[tid + i * 512];
                    mdst[tid + i * 512] =
                        make_float4(A.x - Z.x, A.y - Z.y, A.z - Z.z, A.w - Z.w);
                }
            } else {
#pragma unroll
                for (int i = 0; i < 8; i++) mdst[tid + i * 512] = msrc[tid + i * 512];
            }
        }
        __syncthreads();
        u64 acc2[2][2];
#pragma unroll
        for (int i = 0; i < 2; i++) { acc2[i][0] = 0ull; acc2[i][1] = 0ull; }
        const int hcol = (hh * 4 + h4) * 64;
        const float* mrow = ms + h4 * 4096 + et * 4;
#pragma unroll
        for (int dl = 0; dl < 64; dl++) {
            ulonglong2 m2 = *(ulonglong2*)&mrow[dl * 64];
#pragma unroll
            for (int i = 0; i < 2; i++) {
                u64 qb = pack2b(qs[(tt * 2 + i) * 1024 + hcol + dl]);
                acc2[i][0] = ffma2(qb, m2.x, acc2[i][0]);
                acc2[i][1] = ffma2(qb, m2.y, acc2[i][1]);
            }
        }
        __syncthreads();              // all q reads of this head group done
#pragma unroll
        for (int i = 0; i < 2; i++)
            *(ulonglong2*)&qs[(tt * 2 + i) * 1024 + hcol + et * 4] =
                make_ulonglong2(acc2[i][0], acc2[i][1]);
    }
    __syncthreads();

    // ---- out = Wc head-mix (ctx in qs; outs aliases ms, disjoint writes) ----
    {
        const int d  = tid & 63;
        const int g8 = tid >> 6;
        u64 acc[16];
#pragma unroll
        for (int t = 0; t < 16; t++) acc[t] = 0ull;
#pragma unroll
        for (int h = 0; h < NH; h++) {
            u64 w = *(const u64*)(Wc + d * 256 + h * 16 + g8 * 2);
#pragma unroll
            for (int t = 0; t < 16; t++)
                acc[t] = ffma2(pack2b(qs[t * 1024 + h * 64 + d]), w, acc[t]);
        }
#pragma unroll
        for (int t = 0; t < 16; t++) {
            float2 a = unpk(acc[t]);
            float* o = outs + t * 1024 + g8 * 128 + d;
            o[0] = a.x; o[64] = a.y;
        }
    }
    __syncthreads();

    // ---- gates (one warp per token) ----
    {
        const int t = tid >> 5, sub = tid & 31;
        float a0 = 0.f, a1 = 0.f;
#pragma unroll 8
        for (int k = 0; k < 32; k++) {
            int j = sub + k * 32;
            float hv = xs[t * 1024 + j];
            float ov = outs[t * 1024 + j];
            a0 += hv * Wg[j]        + ov * Ug[j];
            a1 += hv * Wg[1024 + j] + ov * Ug[1024 + j];
        }
#pragma unroll
        for (int off = 16; off >= 1; off >>= 1) {
            a0 += __shfl_xor_sync(0xffffffffu, a0, off);
            a1 += __shfl_xor_sync(0xffffffffu, a1, off);
        }
        if (sub == 0) {
            int s  = (tok0 + t) & (S_LEN - 1);
            int ip = pos_idx(s);
            float z0 = a0 + Vg[ip] + bg[0];
            float z1 = a1 + Vg[P_DIM + ip] + bg[1];
            gs[t * 2]     = 1.f / (1.f + expf(-z0));
            gs[t * 2 + 1] = 1.f / (1.f + expf(-z1));
        }
    }
    __syncthreads();

    // ---- final blend ----
    {
        float4* od = (float4*)out;
#pragma unroll
        for (int i = 0; i < 8; i++) {
            int idx = tid + i * 512;          // float4 index, 4096 total
            int t = idx >> 8;
            float g0 = gs[t * 2], g1 = gs[t * 2 + 1];
            float4 ov = ((float4*)outs)[idx];
            float4 hv = ((float4*)xs)[idx];
            od[(size_t)tok0 * 256 + idx] =
                make_float4(g0 * ov.x + g1 * hv.x, g0 * ov.y + g1 * hv.y,
                            g0 * ov.z + g1 * hv.z, g0 * ov.w + g1 * hv.w);
        }
    }
}

// ---------------------------------------------------------------------------
extern "C" void kernel_launch(void* const* d_in, const int* in_sizes, int n_in,
                              void* d_out, int out_size) {
    const float* hidden   = (const float*)d_in[0];
    const float* Wq       = (const float*)d_in[3];
    const float* Wkg      = (const float*)d_in[4];
    const float* Wkh      = (const float*)d_in[5];
    const float* Wv       = (const float*)d_in[6];
    const float* p_attn   = (const float*)d_in[7];
    const float* p_expand = (const float*)d_in[8];
    const float* Wc       = (const float*)d_in[9];
    const float* Wg       = (const float*)d_in[10];
    const float* Ug       = (const float*)d_in[11];
    const float* Vg       = (const float*)d_in[12];
    const float* bg       = (const float*)d_in[13];
    float* out = (float*)d_out;

    cudaFuncSetAttribute(k1_kernel,      cudaFuncAttributeMaxDynamicSharedMemorySize, 69632);
    cudaFuncSetAttribute(kv_kernel,      cudaFuncAttributeMaxDynamicSharedMemorySize, 73728);
    cudaFuncSetAttribute(ctx_out_kernel, cudaFuncAttributeMaxDynamicSharedMemorySize, 200832);

    k1_kernel<<<dim3(64, 8), 256, 69632>>>(hidden, Wkg);
    kv_kernel<<<256, 512, 73728>>>(hidden, Wkh, Wv, p_attn, p_expand);
    mpart_kernel<<<dim3(32, 16, 2), 128>>>();
    ctx_out_kernel<<<256, 512, 200832>>>(hidden, Wq, p_attn, p_expand,
                                         Wc, Wg, Ug, Vg, bg, out);
}

// round 8
// speedup vs baseline: 1.1440x; 1.0918x over previous
#include <cuda_runtime.h>
#include <math.h>

// ---------------------------------------------------------------------------
// LinearDescent: linear attention with per-(b,h) 64x64 state reassociation.
// B=2, S=2048, H=1024, nh=16, hd=64, kg=8, din=128, P=2112, NPF=64.
// Round 8: R7 redesign with CORRECT M staging: 4 stages x 4 heads (64KB),
// transposed-q smem, broadcast-friendly warp tiles, hidden re-read from L2.
// ---------------------------------------------------------------------------

#define TOK_TOTAL 4096
#define S_LEN     2048
#define H_DIM     1024
#define NH        16
#define P_DIM     2112
#define NPF       64
#define DIN       128
#define QT_STRIDE 20            // padded t-row stride (floats), 16B-aligned rows

typedef unsigned long long u64;

__device__ __forceinline__ u64 pack2b(float v) {
    u64 r; asm("mov.b64 %0, {%1,%1};" : "=l"(r) : "f"(v)); return r;
}
__device__ __forceinline__ u64 ffma2(u64 a, u64 b, u64 c) {
    u64 d; asm("fma.rn.f32x2 %0, %1, %2, %3;" : "=l"(d) : "l"(a), "l"(b), "l"(c)); return d;
}
__device__ __forceinline__ float2 unpk(u64 v) {
    float2 f; asm("mov.b64 {%0,%1}, %2;" : "=f"(f.x), "=f"(f.y) : "l"(v)); return f;
}

// scratch (device globals; allocation-free kernel_launch)
__device__ float g_k1[TOK_TOTAL * H_DIM];
__device__ float g_k [TOK_TOTAL * H_DIM];
__device__ float g_v [TOK_TOTAL * H_DIM];
__device__ float g_Mall[32 * 4096];   // per-(b,h) 64x64 state (atomic accum)
__device__ float g_M0  [32 * 4096];   // prefix-chunk contribution

__device__ __forceinline__ int pos_idx(int s) { return (s < NPF) ? (S_LEN + s) : s; }

// ---------------------------------------------------------------------------
// K1: k1[t, g*128+e] = sum_d hidden[t, g*128+d] * Wk_group[g, d, e]
//     + zeroing duty for g_Mall / g_M0 (precedes mpart in stream order).
// ---------------------------------------------------------------------------
extern "C" __global__ void k1_kernel(const float* __restrict__ hidden,
                                     const float* __restrict__ Wkg) {
    extern __shared__ float sm[];
    float* Ws = sm;            // 128*128
    float* Xs = sm + 16384;    // 64*16
    const int g   = blockIdx.y;
    const int t0  = blockIdx.x * 64;
    const int tid = threadIdx.x;

    if (blockIdx.x < 32) {
        float4 z = make_float4(0.f, 0.f, 0.f, 0.f);
        if (g == 0) {
            float4* p = (float4*)(g_Mall + (size_t)blockIdx.x * 4096);
#pragma unroll
            for (int i = 0; i < 4; i++) p[tid + i * 256] = z;
        } else if (g == 1) {
            float4* p = (float4*)(g_M0 + (size_t)blockIdx.x * 4096);
#pragma unroll
            for (int i = 0; i < 4; i++) p[tid + i * 256] = z;
        }
    }

    {
        const float4* wsrc = (const float4*)(Wkg + (size_t)g * 16384);
        float4* wdst = (float4*)Ws;
#pragma unroll
        for (int i = 0; i < 16; i++) wdst[tid + i * 256] = wsrc[tid + i * 256];
    }

    const int ct = tid & 15;
    const int rt = tid >> 4;
    u64 acc2[4][4];
#pragma unroll
    for (int j = 0; j < 4; j++)
#pragma unroll
        for (int c = 0; c < 4; c++) acc2[j][c] = 0ull;

    for (int kk = 0; kk < 128; kk += 16) {
        __syncthreads();
        {
            int row = tid >> 2, c4 = tid & 3;
            ((float4*)Xs)[tid] =
                *(const float4*)(hidden + (size_t)(t0 + row) * H_DIM + g * DIN + kk + c4 * 4);
        }
        __syncthreads();
#pragma unroll
        for (int i = 0; i < 16; i++) {
            const ulonglong2* wp = (const ulonglong2*)&Ws[(kk + i) * 128 + ct * 8];
            ulonglong2 wA = wp[0], wB = wp[1];
#pragma unroll
            for (int j = 0; j < 4; j++) {
                u64 xb = pack2b(Xs[(rt * 4 + j) * 16 + i]);
                acc2[j][0] = ffma2(xb, wA.x, acc2[j][0]);
                acc2[j][1] = ffma2(xb, wA.y, acc2[j][1]);
                acc2[j][2] = ffma2(xb, wB.x, acc2[j][2]);
                acc2[j][3] = ffma2(xb, wB.y, acc2[j][3]);
            }
        }
    }
#pragma unroll
    for (int j = 0; j < 4; j++) {
        float* o = g_k1 + (size_t)(t0 + rt * 4 + j) * H_DIM + g * DIN + ct * 8;
        ((ulonglong2*)o)[0] = make_ulonglong2(acc2[j][0], acc2[j][1]);
        ((ulonglong2*)o)[1] = make_ulonglong2(acc2[j][2], acc2[j][3]);
    }
}

// ---------------------------------------------------------------------------
// K2: k and v (head/group mixing + positional adds). 16 tokens/block, 256 thr.
// ---------------------------------------------------------------------------
extern "C" __global__ void kv_kernel(const float* __restrict__ hidden,
                                     const float* __restrict__ Wkh,
                                     const float* __restrict__ Wv,
                                     const float* __restrict__ p_attn,
                                     const float* __restrict__ p_expand) {
    extern __shared__ float sm[];
    float* xs = sm;            // 16*1024
    float* ps = sm + 16384;    // 16*128
    const int tid  = threadIdx.x;
    const int tok0 = blockIdx.x * 16;

    {
        const float4* src = (const float4*)(hidden + (size_t)tok0 * H_DIM);
        float4* dst = (float4*)xs;
#pragma unroll
        for (int i = 0; i < 16; i++) dst[tid + i * 256] = src[tid + i * 256];
    }
#pragma unroll
    for (int i = 0; i < 8; i++) {
        int e = tid + i * 256;
        int t = e >> 7, c = e & 127;
        int s = (tok0 + t) & (S_LEN - 1);
        ps[e] = p_attn[(size_t)(64 + c) * P_DIM + pos_idx(s)];
    }
    __syncthreads();

    // ---- V ----
    {
        const int d  = tid & 63;
        const int g4 = tid >> 6;
        u64 acc2[2][16];
#pragma unroll
        for (int pp = 0; pp < 2; pp++)
#pragma unroll
            for (int t = 0; t < 16; t++) acc2[pp][t] = 0ull;
#pragma unroll
        for (int h = 0; h < NH; h++) {
            ulonglong2 w = *(const ulonglong2*)(Wv + d * 256 + h * 16 + g4 * 4);
#pragma unroll
            for (int t = 0; t < 16; t++) {
                u64 xb = pack2b(xs[t * 1024 + h * 64 + d]);
                acc2[0][t] = ffma2(xb, w.x, acc2[0][t]);
                acc2[1][t] = ffma2(xb, w.y, acc2[1][t]);
            }
        }
        float pe[4];
#pragma unroll
        for (int p = 0; p < 4; p++) pe[p] = p_expand[32 + g4 * 4 + p];
#pragma unroll
        for (int t = 0; t < 16; t++) {
            float pv = ps[t * 128 + 64 + d];
            float2 a01 = unpk(acc2[0][t]), a23 = unpk(acc2[1][t]);
            float* o = g_v + (size_t)(tok0 + t) * H_DIM + g4 * 256 + d;
            o[0]   = a01.x + pe[0] * pv;
            o[64]  = a01.y + pe[1] * pv;
            o[128] = a23.x + pe[2] * pv;
            o[192] = a23.y + pe[3] * pv;
        }
    }
    // ---- K ----
    __syncthreads();
    {
        const float4* src = (const float4*)(g_k1 + (size_t)tok0 * H_DIM);
        float4* dst = (float4*)xs;
#pragma unroll
        for (int i = 0; i < 16; i++) dst[tid + i * 256] = src[tid + i * 256];
    }
    __syncthreads();
    {
        const int dd = tid & 127;
        const int h2 = tid >> 7;
        u64 acc2[2][16];
#pragma unroll
        for (int pp = 0; pp < 2; pp++)
#pragma unroll
            for (int t = 0; t < 16; t++) acc2[pp][t] = 0ull;
#pragma unroll
        for (int g = 0; g < 8; g++) {
            ulonglong2 w = *(const ulonglong2*)(Wkh + dd * 64 + g * 8 + h2 * 4);
#pragma unroll
            for (int t = 0; t < 16; t++) {
                u64 xb = pack2b(xs[t * 1024 + g * 128 + dd]);
                acc2[0][t] = ffma2(xb, w.x, acc2[0][t]);
                acc2[1][t] = ffma2(xb, w.y, acc2[1][t]);
            }
        }
#pragma unroll
        for (int t = 0; t < 16; t++) {
            float2 a01 = unpk(acc2[0][t]), a23 = unpk(acc2[1][t]);
            float av[4] = {a01.x, a01.y, a23.x, a23.y};
#pragma unroll
            for (int p = 0; p < 4; p++) {
                int jj  = (h2 * 4 + p) * 128 + dd;
                int h16 = jj >> 6, d64 = jj & 63;
                float pe = p_expand[16 + h16];
                g_k[(size_t)(tok0 + t) * H_DIM + jj] = av[p] + pe * ps[t * 128 + d64];
            }
        }
    }
}

// ---------------------------------------------------------------------------
// K3: M partial per 64-token chunk -> RED.ADD into g_Mall (+plain g_M0, c=0)
// ---------------------------------------------------------------------------
extern "C" __global__ void mpart_kernel() {
    __shared__ float ks[64 * 64];
    __shared__ float vs[64 * 64];
    const int c = blockIdx.x, h = blockIdx.y, b = blockIdx.z;
    const int tid = threadIdx.x;
    const size_t tokbase = (size_t)(b * S_LEN + c * 64);
    const float* kp = g_k + tokbase * H_DIM + h * 64;
    const float* vp = g_v + tokbase * H_DIM + h * 64;
    for (int i = tid; i < 64 * 16; i += 128) {
        int row = i >> 4, c4 = i & 15;
        ((float4*)ks)[i] = *(const float4*)(kp + (size_t)row * H_DIM + c4 * 4);
        ((float4*)vs)[i] = *(const float4*)(vp + (size_t)row * H_DIM + c4 * 4);
    }
    __syncthreads();
    const int et = tid & 15;
    const int dt = tid >> 4;
    u64 acc2[8][2];
#pragma unroll
    for (int i = 0; i < 8; i++) { acc2[i][0] = 0ull; acc2[i][1] = 0ull; }
    for (int t = 0; t < 64; t++) {
        ulonglong2 v2 = *(ulonglong2*)&vs[t * 64 + et * 4];
        float4 ka = *(float4*)&ks[t * 64 + dt * 8];
        float4 kb = *(float4*)&ks[t * 64 + dt * 8 + 4];
        float kv[8] = {ka.x, ka.y, ka.z, ka.w, kb.x, kb.y, kb.z, kb.w};
#pragma unroll
        for (int i = 0; i < 8; i++) {
            u64 kb2 = pack2b(kv[i]);
            acc2[i][0] = ffma2(kb2, v2.x, acc2[i][0]);
            acc2[i][1] = ffma2(kb2, v2.y, acc2[i][1]);
        }
    }
    float* outp = g_Mall + (size_t)(b * 16 + h) * 4096;
    float* out0 = g_M0   + (size_t)(b * 16 + h) * 4096;
#pragma unroll
    for (int i = 0; i < 8; i++) {
        float2 a0 = unpk(acc2[i][0]), a1 = unpk(acc2[i][1]);
        int off = (dt * 8 + i) * 64 + et * 4;
        atomicAdd(&outp[off],     a0.x);
        atomicAdd(&outp[off + 1], a0.y);
        atomicAdd(&outp[off + 2], a1.x);
        atomicAdd(&outp[off + 3], a1.y);
        if (c == 0)
            *(ulonglong2*)&out0[off] = make_ulonglong2(acc2[i][0], acc2[i][1]);
    }
}

// ---------------------------------------------------------------------------
// K4: q (transposed into qT), ctx = q @ M via 4 stages x 4 heads with
// broadcast-friendly warp tiles, Wc head-mix, gates, blend.
// 16 tokens/block, 512 threads, 217KB smem, 1 CTA/SM.
// smem floats:
//   Mbuf [0, 16384)      hidden -> M(4-head stages) -> outs
//   qT   [16384, 36864)  transposed q: row (h*64+d)*20, col t  (80KB)
//   C    [36864, 53248)  ctx natural [t][h*64+e]
//   psq  [53248, 54272), gs [54272, 54304)
// ---------------------------------------------------------------------------
extern "C" __global__ void __launch_bounds__(512, 1)
ctx_out_kernel(const float* __restrict__ hidden,
               const float* __restrict__ Wq,
               const float* __restrict__ p_attn,
               const float* __restrict__ p_expand,
               const float* __restrict__ Wc,
               const float* __restrict__ Wg,
               const float* __restrict__ Ug,
               const float* __restrict__ Vg,
               const float* __restrict__ bg,
               float* __restrict__ out) {
    extern __shared__ float sm[];
    float* Mbuf = sm;
    float* qT   = sm + 16384;
    float* C    = sm + 36864;
    float* psq  = sm + 53248;
    float* gs   = sm + 54272;
    const int tid  = threadIdx.x;
    const int tok0 = blockIdx.x * 16;
    const int b    = tok0 / S_LEN;
    const int s0   = tok0 & (S_LEN - 1);
    const bool prefix = (s0 < NPF);

    {   // stage hidden into Mbuf (4096 float4)
        const float4* src = (const float4*)(hidden + (size_t)tok0 * H_DIM);
        float4* dst = (float4*)Mbuf;
#pragma unroll
        for (int i = 0; i < 8; i++) dst[tid + i * 512] = src[tid + i * 512];
    }
#pragma unroll
    for (int i = 0; i < 2; i++) {   // psq: 1024 entries
        int e = tid + i * 512;
        int t = e >> 6, d = e & 63;
        int s = (tok0 + t) & (S_LEN - 1);
        psq[e] = p_attn[(size_t)d * P_DIM + pos_idx(s)];
    }
    __syncthreads();

    // ---- Q -> qT (transposed, padded rows) ----
    {
        const int d  = tid & 63;
        const int g8 = tid >> 6;            // head pair base = g8*2
        const float pe0 = p_expand[g8 * 2];
        const float pe1 = p_expand[g8 * 2 + 1];
        u64 acc[16];
#pragma unroll
        for (int t = 0; t < 16; t++) acc[t] = 0ull;
#pragma unroll
        for (int h = 0; h < NH; h++) {
            u64 w = *(const u64*)(Wq + d * 256 + h * 16 + g8 * 2);
#pragma unroll
            for (int t = 0; t < 16; t++)
                acc[t] = ffma2(pack2b(Mbuf[t * 1024 + h * 64 + d]), w, acc[t]);
        }
        float* row0 = qT + ((g8 * 2) * 64 + d) * QT_STRIDE;
        float* row1 = qT + ((g8 * 2 + 1) * 64 + d) * QT_STRIDE;
#pragma unroll
        for (int t = 0; t < 16; t++) {
            float pq = psq[t * 64 + d];
            float2 a = unpk(acc[t]);
            row0[t] = a.x + pe0 * pq;
            row1[t] = a.y + pe1 * pq;
        }
    }

    // ---- ctx = q @ M : 4 stages x 4 heads ----
    // warp wid: hh = wid>>2 (head in stage), qe = wid&3 (e quarter)
    // lane: tg = lane>>3 (tokens tg*4..+3), eg = lane&7 (e = qe*16 + eg*2)
    const int wid  = tid >> 5;
    const int lane = tid & 31;
    const int hh   = wid >> 2;
    const int qe   = wid & 3;
    const int tg   = lane >> 3;
    const int eg   = lane & 7;
    const float* Ma = g_Mall + (size_t)(b * 16) * 4096;
    const float* M0 = g_M0   + (size_t)(b * 16) * 4096;

    for (int stg = 0; stg < 4; stg++) {
        __syncthreads();   // stage 0: hidden+qT done; later: prior ctx reads done
        {   // stage 4 heads of M into Mbuf (4096 float4, 8/thread)
            const float4* msrc = (const float4*)(Ma + (size_t)stg * 16384);
            const float4* zsrc = (const float4*)(M0 + (size_t)stg * 16384);
            float4* mdst = (float4*)Mbuf;
            if (prefix) {
#pragma unroll
                for (int i = 0; i < 8; i++) {
                    float4 Av = msrc[tid + i * 512], Z = zsrc[tid + i * 512];
                    mdst[tid + i * 512] =
                        make_float4(Av.x - Z.x, Av.y - Z.y, Av.z - Z.z, Av.w - Z.w);
                }
            } else {
#pragma unroll
                for (int i = 0; i < 8; i++) mdst[tid + i * 512] = msrc[tid + i * 512];
            }
        }
        __syncthreads();

        const int head = stg * 4 + hh;
        const float* qrow = qT + (head * 64) * QT_STRIDE + tg * 4;
        const float* mrow = Mbuf + hh * 4096 + qe * 16 + eg * 2;
        u64 acc[4];
#pragma unroll
        for (int i = 0; i < 4; i++) acc[i] = 0ull;
#pragma unroll 8
        for (int dl = 0; dl < 64; dl++) {
            float4 q4 = *(const float4*)(qrow + dl * QT_STRIDE);   // broadcast x8
            u64 m2 = *(const u64*)(mrow + dl * 64);                // broadcast x4
            acc[0] = ffma2(pack2b(q4.x), m2, acc[0]);
            acc[1] = ffma2(pack2b(q4.y), m2, acc[1]);
            acc[2] = ffma2(pack2b(q4.z), m2, acc[2]);
            acc[3] = ffma2(pack2b(q4.w), m2, acc[3]);
        }
#pragma unroll
        for (int i = 0; i < 4; i++)
            *(u64*)&C[(tg * 4 + i) * 1024 + head * 64 + qe * 16 + eg * 2] = acc[i];
    }
    __syncthreads();   // ctx complete in C; Mbuf free

    // ---- out = Wc head-mix: read C, write outs into Mbuf ----
    {
        const int d  = tid & 63;
        const int g8 = tid >> 6;
        u64 acc[16];
#pragma unroll
        for (int t = 0; t < 16; t++) acc[t] = 0ull;
#pragma unroll
        for (int h = 0; h < NH; h++) {
            u64 w = *(const u64*)(Wc + d * 256 + h * 16 + g8 * 2);
#pragma unroll
            for (int t = 0; t < 16; t++)
                acc[t] = ffma2(pack2b(C[t * 1024 + h * 64 + d]), w, acc[t]);
        }
#pragma unroll
        for (int t = 0; t < 16; t++) {
            float2 a = unpk(acc[t]);
            float* o = Mbuf + t * 1024 + g8 * 128 + d;
            o[0] = a.x; o[64] = a.y;
        }
    }
    __syncthreads();

    // ---- gates: one warp per token; hidden re-read from global (L2-hot) ----
    {
        const int t = tid >> 5, sub = tid & 31;
        const float* hrow = hidden + (size_t)(tok0 + t) * H_DIM;
        float a0 = 0.f, a1 = 0.f;
#pragma unroll 8
        for (int k = 0; k < 32; k++) {
            int j = sub + k * 32;
            float hv = hrow[j];
            float ov = Mbuf[t * 1024 + j];
            a0 += hv * Wg[j]        + ov * Ug[j];
            a1 += hv * Wg[1024 + j] + ov * Ug[1024 + j];
        }
#pragma unroll
        for (int off = 16; off >= 1; off >>= 1) {
            a0 += __shfl_xor_sync(0xffffffffu, a0, off);
            a1 += __shfl_xor_sync(0xffffffffu, a1, off);
        }
        if (sub == 0) {
            int s  = (tok0 + t) & (S_LEN - 1);
            int ip = pos_idx(s);
            float z0 = a0 + Vg[ip] + bg[0];
            float z1 = a1 + Vg[P_DIM + ip] + bg[1];
            gs[t * 2]     = 1.f / (1.f + expf(-z0));
            gs[t * 2 + 1] = 1.f / (1.f + expf(-z1));
        }
    }
    __syncthreads();

    // ---- final blend (hidden from global, outs from Mbuf) ----
    {
        const float4* hsrc = (const float4*)(hidden + (size_t)tok0 * H_DIM);
        float4* od = (float4*)out;
#pragma unroll
        for (int i = 0; i < 8; i++) {
            int idx = tid + i * 512;          // float4 index, 4096 total
            int t = idx >> 8;
            float g0 = gs[t * 2], g1 = gs[t * 2 + 1];
            float4 ov = ((float4*)Mbuf)[idx];
            float4 hv = hsrc[idx];
            od[(size_t)tok0 * 256 + idx] =
                make_float4(g0 * ov.x + g1 * hv.x, g0 * ov.y + g1 * hv.y,
                            g0 * ov.z + g1 * hv.z, g0 * ov.w + g1 * hv.w);
        }
    }
}

// ---------------------------------------------------------------------------
extern "C" void kernel_launch(void* const* d_in, const int* in_sizes, int n_in,
                              void* d_out, int out_size) {
    const float* hidden   = (const float*)d_in[0];
    const float* Wq       = (const float*)d_in[3];
    const float* Wkg      = (const float*)d_in[4];
    const float* Wkh      = (const float*)d_in[5];
    const float* Wv       = (const float*)d_in[6];
    const float* p_attn   = (const float*)d_in[7];
    const float* p_expand = (const float*)d_in[8];
    const float* Wc       = (const float*)d_in[9];
    const float* Wg       = (const float*)d_in[10];
    const float* Ug       = (const float*)d_in[11];
    const float* Vg       = (const float*)d_in[12];
    const float* bg       = (const float*)d_in[13];
    float* out = (float*)d_out;

    cudaFuncSetAttribute(k1_kernel,      cudaFuncAttributeMaxDynamicSharedMemorySize, 69632);
    cudaFuncSetAttribute(kv_kernel,      cudaFuncAttributeMaxDynamicSharedMemorySize, 73728);
    cudaFuncSetAttribute(ctx_out_kernel, cudaFuncAttributeMaxDynamicSharedMemorySize, 217216);

    k1_kernel<<<dim3(64, 8), 256, 69632>>>(hidden, Wkg);
    kv_kernel<<<256, 256, 73728>>>(hidden, Wkh, Wv, p_attn, p_expand);
    mpart_kernel<<<dim3(32, 16, 2), 128>>>();
    ctx_out_kernel<<<256, 512, 217216>>>(hidden, Wq, p_attn, p_expand,
                                         Wc, Wg, Ug, Vg, bg, out);
}